// round 14
// baseline (speedup 1.0000x reference)
#include <cuda_runtime.h>
#include <math.h>

#define BB 64
#define SS 2048
#define HH 1024
#define SPLITS 32
#define ROWS_PER_WARP (SS / SPLITS)           // 64
#define WARPS_PER_CTA 8

// ---------------- scratch (no allocations allowed) ----------------
__device__ float g_scores[BB * SS];             // raw attention scores
__device__ float g_pacc[BB * SPLITS * HH];      // partial weighted sums (8 MB)
__device__ float g_pm[BB * SPLITS];             // partial running max
__device__ float g_pl[BB * SPLITS];             // partial exp-sum
__device__ float g_attn[BB * HH];               // combined attention output
__device__ float g_fc1_part[16 * BB * HH];      // fc1 split-K partials
__device__ float g_y[BB * HH];                  // post-BN-tanh activations
__device__ float g_fc2_part[16 * BB * HH];      // fc2 split-K partials

#define FMA2(d, a, b) \
    asm("fma.rn.f32x2 %0, %1, %2, %0;" : "+l"(d) : "l"(a), "l"(b))

// ================= Kernel 1: locality-transposed attention ==================
// grid (SPLITS, BB/8), block 256 = 8 warps. Warp w owns batch b = by*8+w and
// sweeps s in [bx*64, bx*64+64). All 8 warps of a CTA move through the SAME s
// in near-lockstep, so each step the CTA reads rows (s, b0..b0+7): one
// contiguous 32 KB block. ctx streamed with __ldcs (read-once).
// Frozen at R12 form: best of five measured attn variants.
__global__ __launch_bounds__(256) void attn_pass(
    const float* __restrict__ ctx, const float* __restrict__ key,
    const float* __restrict__ mask)
{
    const int w    = threadIdx.x >> 5;
    const int lane = threadIdx.x & 31;
    const int b     = blockIdx.y * WARPS_PER_CTA + w;
    const int split = blockIdx.x;
    const int s0    = split * ROWS_PER_WARP;

    const float4* ctx4 = (const float4*)ctx;
    const float4* key4 = (const float4*)key;

    float4 kk[8];
#pragma unroll
    for (int j = 0; j < 8; j++)
        kk[j] = key4[b * (HH / 4) + j * 32 + lane];

    float4 acc[8];
#pragma unroll
    for (int j = 0; j < 8; j++) acc[j] = make_float4(0.f, 0.f, 0.f, 0.f);
    float m = -1e30f, l = 0.f;

    for (int r = 0; r < ROWS_PER_WARP; r++) {
        const int s = s0 + r;
        const float4* row = ctx4 + (size_t)(s * BB + b) * (HH / 4);
        float4 rv[8];
#pragma unroll
        for (int j = 0; j < 8; j++) rv[j] = __ldcs(&row[j * 32 + lane]);

        float d = 0.f;
#pragma unroll
        for (int j = 0; j < 8; j++)
            d += rv[j].x * kk[j].x + rv[j].y * kk[j].y +
                 rv[j].z * kk[j].z + rv[j].w * kk[j].w;
#pragma unroll
        for (int off = 16; off > 0; off >>= 1)
            d += __shfl_xor_sync(0xffffffffu, d, off);

        d += mask[b * SS + s];
        if (lane == 0) g_scores[b * SS + s] = d;

        if (d > m) {
            const float f = __expf(m - d);
            m = d;
            l *= f;
#pragma unroll
            for (int j = 0; j < 8; j++) {
                acc[j].x *= f; acc[j].y *= f; acc[j].z *= f; acc[j].w *= f;
            }
        }
        const float p = __expf(d - m);
        l += p;
#pragma unroll
        for (int j = 0; j < 8; j++) {
            acc[j].x += p * rv[j].x; acc[j].y += p * rv[j].y;
            acc[j].z += p * rv[j].z; acc[j].w += p * rv[j].w;
        }
    }

    float4* pacc4 = (float4*)g_pacc;
#pragma unroll
    for (int j = 0; j < 8; j++)
        pacc4[(size_t)(b * SPLITS + split) * (HH / 4) + j * 32 + lane] = acc[j];
    if (lane == 0) {
        g_pm[b * SPLITS + split] = m;
        g_pl[b * SPLITS + split] = l;
    }
}

// ====== Kernel 2: combine split partials -> attn | normalize At ============
// grid (B, 3), block 256. phase 0/1: attn combine (half of H each, float2).
// phase 2: At normalize.
__global__ __launch_bounds__(256) void combine_kernel(float* __restrict__ out_At)
{
    const int b = blockIdx.x;
    const int tid = threadIdx.x;

    float M = -1e30f;
#pragma unroll
    for (int i = 0; i < SPLITS; i++)
        M = fmaxf(M, g_pm[b * SPLITS + i]);
    float L = 0.f;
#pragma unroll
    for (int i = 0; i < SPLITS; i++)
        L += __expf(g_pm[b * SPLITS + i] - M) * g_pl[b * SPLITS + i];
    const float invL = 1.f / L;

    if (blockIdx.y < 2) {
        const int i2 = blockIdx.y * 256 + tid;     // float2 index, 512 = HH/2
        float2 a = make_float2(0.f, 0.f);
#pragma unroll
        for (int i = 0; i < SPLITS; i++) {
            const float f = __expf(g_pm[b * SPLITS + i] - M);
            const float2 v =
                ((const float2*)g_pacc)[(size_t)(b * SPLITS + i) * (HH / 2) + i2];
            a.x += f * v.x; a.y += f * v.y;
        }
        a.x *= invL; a.y *= invL;
        ((float2*)g_attn)[b * (HH / 2) + i2] = a;
    } else {
        const float4* sc4 = (const float4*)(g_scores + b * SS);
        float4* at4 = (float4*)(out_At + b * SS);
#pragma unroll
        for (int it = 0; it < SS / 4 / 256; it++) {
            const float4 s = sc4[it * 256 + tid];
            at4[it * 256 + tid] = make_float4(
                __expf(s.x - M) * invL, __expf(s.y - M) * invL,
                __expf(s.z - M) * invL, __expf(s.w - M) * invL);
        }
    }
}

// ============ Kernel 3/5: split-K GEMM  out[b,j] = sum_k A[b,k]*W[j,k] ======
// block 256 (16x16), tile 64b x 64j x KCHUNK. k-major smem, A duplicated so
// both fma.rn.f32x2 operands come pre-packed from shared memory.
template <int K, int KCHUNK, bool CAT>
__global__ __launch_bounds__(256) void gemm_splitk(
    const float* __restrict__ key, const float* __restrict__ W)
{
    const float* A  = CAT ? g_attn : g_y;
    float* part     = CAT ? g_fc1_part : g_fc2_part;

    const int tid = threadIdx.x;
    const int j0 = blockIdx.x * 64;
    const int k0 = blockIdx.y * KCHUNK;
    const int tx = tid & 15, ty = tid >> 4;

    __shared__ float As[32][132];   // As[k][2r] = As[k][2r+1] = A[r][k]
    __shared__ float Ws[32][68];    // Ws[k][r]  = W[j0+r][k]

    unsigned long long acc[4][2];
#pragma unroll
    for (int i = 0; i < 4; i++) { acc[i][0] = 0ull; acc[i][1] = 0ull; }

    for (int kk = 0; kk < KCHUNK; kk += 32) {
#pragma unroll
        for (int t = 0; t < 8; t++) {
            const int e = tid + t * 256;
            const int r = e >> 5, c = e & 31;
            const int kg = k0 + kk + c;
            float av;
            if (CAT)
                av = (kg < HH) ? A[r * HH + kg] : key[r * HH + kg - HH];
            else
                av = A[r * K + kg];
            *(float2*)&As[c][2 * r] = make_float2(av, av);
            Ws[c][r] = W[(size_t)(j0 + r) * K + kg];
        }
        __syncthreads();
#pragma unroll
        for (int k = 0; k < 32; k++) {
            const ulonglong2 a01 = *(const ulonglong2*)&As[k][ty * 8];
            const ulonglong2 a23 = *(const ulonglong2*)&As[k][ty * 8 + 4];
            const ulonglong2 wp  = *(const ulonglong2*)&Ws[k][tx * 4];
            FMA2(acc[0][0], a01.x, wp.x); FMA2(acc[0][1], a01.x, wp.y);
            FMA2(acc[1][0], a01.y, wp.x); FMA2(acc[1][1], a01.y, wp.y);
            FMA2(acc[2][0], a23.x, wp.x); FMA2(acc[2][1], a23.x, wp.y);
            FMA2(acc[3][0], a23.y, wp.x); FMA2(acc[3][1], a23.y, wp.y);
        }
        __syncthreads();
    }

#pragma unroll
    for (int bi = 0; bi < 4; bi++) {
        const int b = ty * 4 + bi;
        float* dst = part + (size_t)(blockIdx.y * BB + b) * HH + j0 + tx * 4;
#pragma unroll
        for (int jp = 0; jp < 2; jp++) {
            float2 v;
            v.x = __uint_as_float((unsigned)(acc[bi][jp] & 0xffffffffull));
            v.y = __uint_as_float((unsigned)(acc[bi][jp] >> 32));
            *(float2*)(dst + jp * 2) = v;
        }
    }
}

// ======== Kernel 4: reduce fc1 partials + BatchNorm(train) + tanh ==========
// grid 64, block 256: thread = (batch b, float4 feature-group jl).
// 16 vectorized independent loads per thread (vs 32 scalar strided before);
// the reduced value stays in registers for the tanh write.
// fc1_b is skipped: any per-feature constant cancels exactly in (x - mean).
__global__ __launch_bounds__(256) void bn_tanh_kernel(
    const float* __restrict__ gamma, const float* __restrict__ beta)
{
    __shared__ float4 rsum[BB][5];    // [batch][float4-group], padded
    __shared__ float4 rsq[BB][5];

    const int jl = threadIdx.x & 3;        // float4 group within CTA (0..3)
    const int b  = threadIdx.x >> 2;       // batch (0..63)
    const int j4 = blockIdx.x * 4 + jl;    // global float4 index (0..255)

    const float4* p4 = (const float4*)g_fc1_part;
    float4 x = make_float4(0.f, 0.f, 0.f, 0.f);
#pragma unroll
    for (int sp = 0; sp < 16; sp++) {
        const float4 v = p4[(size_t)(sp * BB + b) * (HH / 4) + j4];
        x.x += v.x; x.y += v.y; x.z += v.z; x.w += v.w;
    }
    rsum[b][jl] = x;
    rsq[b][jl]  = make_float4(x.x * x.x, x.y * x.y, x.z * x.z, x.w * x.w);
    __syncthreads();

    float4 mean = make_float4(0.f, 0.f, 0.f, 0.f);
    float4 msq  = make_float4(0.f, 0.f, 0.f, 0.f);
#pragma unroll
    for (int g = 0; g < BB; g++) {
        const float4 s = rsum[g][jl];
        const float4 q = rsq[g][jl];
        mean.x += s.x; mean.y += s.y; mean.z += s.z; mean.w += s.w;
        msq.x  += q.x; msq.y  += q.y; msq.z  += q.z; msq.w  += q.w;
    }
    const float r = 1.f / BB;
    mean.x *= r; mean.y *= r; mean.z *= r; mean.w *= r;
    msq.x  *= r; msq.y  *= r; msq.z  *= r; msq.w  *= r;

    const float4 g4  = ((const float4*)gamma)[j4];
    const float4 be4 = ((const float4*)beta)[j4];

    const float ivx = rsqrtf(msq.x - mean.x * mean.x + 1e-5f) * g4.x;
    const float ivy = rsqrtf(msq.y - mean.y * mean.y + 1e-5f) * g4.y;
    const float ivz = rsqrtf(msq.z - mean.z * mean.z + 1e-5f) * g4.z;
    const float ivw = rsqrtf(msq.w - mean.w * mean.w + 1e-5f) * g4.w;

    float4 yv;
    yv.x = tanhf((x.x - mean.x) * ivx + be4.x);
    yv.y = tanhf((x.y - mean.y) * ivy + be4.y);
    yv.z = tanhf((x.z - mean.z) * ivz + be4.z);
    yv.w = tanhf((x.w - mean.w) * ivw + be4.w);
    ((float4*)g_y)[b * (HH / 4) + j4] = yv;
}

// ======== Kernel 6: reduce fc2 partials + bias -> output x ==================
__global__ __launch_bounds__(256) void finalize_kernel(
    const float* __restrict__ fc2_b, float* __restrict__ out_x)
{
    const int i = blockIdx.x * 256 + threadIdx.x;   // 16384 float4s
    const float4* b4 = (const float4*)fc2_b;
    const float4* p4 = (const float4*)g_fc2_part;
    float4 v = b4[i & (HH / 4 - 1)];
#pragma unroll
    for (int kt = 0; kt < 16; kt++) {
        const float4 p = p4[(size_t)kt * BB * HH / 4 + i];
        v.x += p.x; v.y += p.y; v.z += p.z; v.w += p.w;
    }
    ((float4*)out_x)[i] = v;
}

// ============================ launch ========================================
extern "C" void kernel_launch(void* const* d_in, const int* in_sizes, int n_in,
                              void* d_out, int out_size)
{
    const float* ctx   = (const float*)d_in[0];
    const float* key   = (const float*)d_in[1];
    const float* mask  = (const float*)d_in[2];
    const float* fc1_w = (const float*)d_in[3];
    // d_in[4] = fc1_b (cancels in BatchNorm, unused)
    const float* bn_g  = (const float*)d_in[5];
    const float* bn_b  = (const float*)d_in[6];
    const float* fc2_w = (const float*)d_in[7];
    const float* fc2_b = (const float*)d_in[8];

    float* out_x  = (float*)d_out;              // (B, H)  = 65536 floats
    float* out_At = (float*)d_out + BB * HH;    // (B, S)  = 131072 floats

    attn_pass<<<dim3(SPLITS, BB / WARPS_PER_CTA), 256>>>(ctx, key, mask);
    combine_kernel<<<dim3(BB, 3), 256>>>(out_At);

    // fc1: cat([attn, key]) @ fc1_w.T   (K = 2048, 16 k-splits of 128)
    gemm_splitk<2048, 128, true><<<dim3(16, 16), 256>>>(key, fc1_w);
    bn_tanh_kernel<<<64, 256>>>(bn_g, bn_b);

    // fc2: y @ fc2_w.T                  (K = 1024, 16 k-splits of 64)
    gemm_splitk<1024, 64, false><<<dim3(16, 16), 256>>>(key, fc2_w);
    finalize_kernel<<<64, 256>>>(fc2_b, out_x);
}

// round 15
// speedup vs baseline: 1.0251x; 1.0251x over previous
#include <cuda_runtime.h>
#include <math.h>

#define BB 64
#define SS 2048
#define HH 1024
#define SPLITS 32
#define ROWS_PER_WARP (SS / SPLITS)           // 64
#define WARPS_PER_CTA 8

// ---------------- scratch (no allocations allowed) ----------------
__device__ float g_scores[BB * SS];             // raw attention scores
__device__ float g_pacc[BB * SPLITS * HH];      // partial weighted sums (8 MB)
__device__ float g_pm[BB * SPLITS];             // partial running max
__device__ float g_pl[BB * SPLITS];             // partial exp-sum
__device__ float g_attn[BB * HH];               // combined attention output
__device__ float g_fc1_part[16 * BB * HH];      // fc1 split-K partials
__device__ float g_y[BB * HH];                  // post-BN-tanh activations
__device__ float g_fc2_part[16 * BB * HH];      // fc2 split-K partials

#define FMA2(d, a, b) \
    asm("fma.rn.f32x2 %0, %1, %2, %0;" : "+l"(d) : "l"(a), "l"(b))

// ================= Kernel 1: locality-transposed attention ==================
// grid (SPLITS, BB/8), block 256 = 8 warps. Warp w owns batch b = by*8+w and
// sweeps s in [bx*64, bx*64+64). All 8 warps of a CTA move through the SAME s
// in near-lockstep, so each step the CTA reads rows (s, b0..b0+7): one
// contiguous 32 KB block. ctx streamed with __ldcs (read-once).
// Frozen at R12 form: best of five measured attn variants.
__global__ __launch_bounds__(256) void attn_pass(
    const float* __restrict__ ctx, const float* __restrict__ key,
    const float* __restrict__ mask)
{
    const int w    = threadIdx.x >> 5;
    const int lane = threadIdx.x & 31;
    const int b     = blockIdx.y * WARPS_PER_CTA + w;
    const int split = blockIdx.x;
    const int s0    = split * ROWS_PER_WARP;

    const float4* ctx4 = (const float4*)ctx;
    const float4* key4 = (const float4*)key;

    float4 kk[8];
#pragma unroll
    for (int j = 0; j < 8; j++)
        kk[j] = key4[b * (HH / 4) + j * 32 + lane];

    float4 acc[8];
#pragma unroll
    for (int j = 0; j < 8; j++) acc[j] = make_float4(0.f, 0.f, 0.f, 0.f);
    float m = -1e30f, l = 0.f;

    for (int r = 0; r < ROWS_PER_WARP; r++) {
        const int s = s0 + r;
        const float4* row = ctx4 + (size_t)(s * BB + b) * (HH / 4);
        float4 rv[8];
#pragma unroll
        for (int j = 0; j < 8; j++) rv[j] = __ldcs(&row[j * 32 + lane]);

        float d = 0.f;
#pragma unroll
        for (int j = 0; j < 8; j++)
            d += rv[j].x * kk[j].x + rv[j].y * kk[j].y +
                 rv[j].z * kk[j].z + rv[j].w * kk[j].w;
#pragma unroll
        for (int off = 16; off > 0; off >>= 1)
            d += __shfl_xor_sync(0xffffffffu, d, off);

        d += mask[b * SS + s];
        if (lane == 0) g_scores[b * SS + s] = d;

        if (d > m) {
            const float f = __expf(m - d);
            m = d;
            l *= f;
#pragma unroll
            for (int j = 0; j < 8; j++) {
                acc[j].x *= f; acc[j].y *= f; acc[j].z *= f; acc[j].w *= f;
            }
        }
        const float p = __expf(d - m);
        l += p;
#pragma unroll
        for (int j = 0; j < 8; j++) {
            acc[j].x += p * rv[j].x; acc[j].y += p * rv[j].y;
            acc[j].z += p * rv[j].z; acc[j].w += p * rv[j].w;
        }
    }

    float4* pacc4 = (float4*)g_pacc;
#pragma unroll
    for (int j = 0; j < 8; j++)
        pacc4[(size_t)(b * SPLITS + split) * (HH / 4) + j * 32 + lane] = acc[j];
    if (lane == 0) {
        g_pm[b * SPLITS + split] = m;
        g_pl[b * SPLITS + split] = l;
    }
}

// ====== Kernel 2: combine split partials -> attn | normalize At ============
// grid (B, 3), block 256. phase 0/1: attn combine (half of H each, float2).
// phase 2: At normalize. (Split measured ~-2 us vs single-phase in R14.)
__global__ __launch_bounds__(256) void combine_kernel(float* __restrict__ out_At)
{
    const int b = blockIdx.x;
    const int tid = threadIdx.x;

    float M = -1e30f;
#pragma unroll
    for (int i = 0; i < SPLITS; i++)
        M = fmaxf(M, g_pm[b * SPLITS + i]);
    float L = 0.f;
#pragma unroll
    for (int i = 0; i < SPLITS; i++)
        L += __expf(g_pm[b * SPLITS + i] - M) * g_pl[b * SPLITS + i];
    const float invL = 1.f / L;

    if (blockIdx.y < 2) {
        const int i2 = blockIdx.y * 256 + tid;     // float2 index, 512 = HH/2
        float2 a = make_float2(0.f, 0.f);
#pragma unroll
        for (int i = 0; i < SPLITS; i++) {
            const float f = __expf(g_pm[b * SPLITS + i] - M);
            const float2 v =
                ((const float2*)g_pacc)[(size_t)(b * SPLITS + i) * (HH / 2) + i2];
            a.x += f * v.x; a.y += f * v.y;
        }
        a.x *= invL; a.y *= invL;
        ((float2*)g_attn)[b * (HH / 2) + i2] = a;
    } else {
        const float4* sc4 = (const float4*)(g_scores + b * SS);
        float4* at4 = (float4*)(out_At + b * SS);
#pragma unroll
        for (int it = 0; it < SS / 4 / 256; it++) {
            const float4 s = sc4[it * 256 + tid];
            at4[it * 256 + tid] = make_float4(
                __expf(s.x - M) * invL, __expf(s.y - M) * invL,
                __expf(s.z - M) * invL, __expf(s.w - M) * invL);
        }
    }
}

// ============ Kernel 3/5: split-K GEMM  out[b,j] = sum_k A[b,k]*W[j,k] ======
// block 256 (16x16), tile 64b x 64j x KCHUNK. k-major smem, A duplicated so
// both fma.rn.f32x2 operands come pre-packed from shared memory.
template <int K, int KCHUNK, bool CAT>
__global__ __launch_bounds__(256) void gemm_splitk(
    const float* __restrict__ key, const float* __restrict__ W)
{
    const float* A  = CAT ? g_attn : g_y;
    float* part     = CAT ? g_fc1_part : g_fc2_part;

    const int tid = threadIdx.x;
    const int j0 = blockIdx.x * 64;
    const int k0 = blockIdx.y * KCHUNK;
    const int tx = tid & 15, ty = tid >> 4;

    __shared__ float As[32][132];   // As[k][2r] = As[k][2r+1] = A[r][k]
    __shared__ float Ws[32][68];    // Ws[k][r]  = W[j0+r][k]

    unsigned long long acc[4][2];
#pragma unroll
    for (int i = 0; i < 4; i++) { acc[i][0] = 0ull; acc[i][1] = 0ull; }

    for (int kk = 0; kk < KCHUNK; kk += 32) {
#pragma unroll
        for (int t = 0; t < 8; t++) {
            const int e = tid + t * 256;
            const int r = e >> 5, c = e & 31;
            const int kg = k0 + kk + c;
            float av;
            if (CAT)
                av = (kg < HH) ? A[r * HH + kg] : key[r * HH + kg - HH];
            else
                av = A[r * K + kg];
            *(float2*)&As[c][2 * r] = make_float2(av, av);
            Ws[c][r] = W[(size_t)(j0 + r) * K + kg];
        }
        __syncthreads();
#pragma unroll
        for (int k = 0; k < 32; k++) {
            const ulonglong2 a01 = *(const ulonglong2*)&As[k][ty * 8];
            const ulonglong2 a23 = *(const ulonglong2*)&As[k][ty * 8 + 4];
            const ulonglong2 wp  = *(const ulonglong2*)&Ws[k][tx * 4];
            FMA2(acc[0][0], a01.x, wp.x); FMA2(acc[0][1], a01.x, wp.y);
            FMA2(acc[1][0], a01.y, wp.x); FMA2(acc[1][1], a01.y, wp.y);
            FMA2(acc[2][0], a23.x, wp.x); FMA2(acc[2][1], a23.x, wp.y);
            FMA2(acc[3][0], a23.y, wp.x); FMA2(acc[3][1], a23.y, wp.y);
        }
        __syncthreads();
    }

#pragma unroll
    for (int bi = 0; bi < 4; bi++) {
        const int b = ty * 4 + bi;
        float* dst = part + (size_t)(blockIdx.y * BB + b) * HH + j0 + tx * 4;
#pragma unroll
        for (int jp = 0; jp < 2; jp++) {
            float2 v;
            v.x = __uint_as_float((unsigned)(acc[bi][jp] & 0xffffffffull));
            v.y = __uint_as_float((unsigned)(acc[bi][jp] >> 32));
            *(float2*)(dst + jp * 2) = v;
        }
    }
}

// ======== Kernel 4: reduce fc1 partials + BatchNorm(train) + tanh ==========
// grid 128, block 256: CTA = 8 features x 64 batches, 2 batches/thread-group.
// (R13 form — fastest measured bn_tanh at 6.1 us; R14's float4 layout
// regressed to 10 us and was reverted.)
// fc1_b is skipped: any per-feature constant cancels exactly in (x - mean).
__global__ __launch_bounds__(256) void bn_tanh_kernel(
    const float* __restrict__ gamma, const float* __restrict__ beta)
{
    __shared__ float rsum[32][9];
    __shared__ float rsq[32][9];

    const int t  = threadIdx.x;
    const int jl = t & 7;
    const int bt = t >> 3;            // 0..31, each covers 2 batches
    const int j  = blockIdx.x * 8 + jl;

    float xv[2];
    float ps = 0.f, pq = 0.f;
#pragma unroll
    for (int bi = 0; bi < 2; bi++) {
        const int b = bt * 2 + bi;
        float s = 0.f;
#pragma unroll
        for (int sp = 0; sp < 16; sp++)
            s += g_fc1_part[((size_t)sp * BB + b) * HH + j];
        xv[bi] = s;
        ps += s;
        pq += s * s;
    }
    rsum[bt][jl] = ps;
    rsq[bt][jl]  = pq;
    __syncthreads();

    float mean = 0.f, msq = 0.f;
#pragma unroll
    for (int g = 0; g < 32; g++) {
        mean += rsum[g][jl];
        msq  += rsq[g][jl];
    }
    mean *= (1.f / BB);
    msq  *= (1.f / BB);
    const float var = msq - mean * mean;
    const float inv = rsqrtf(var + 1e-5f);
    const float gm  = gamma[j] * inv;
    const float be  = beta[j] - mean * gm;

#pragma unroll
    for (int bi = 0; bi < 2; bi++) {
        const int b = bt * 2 + bi;
        g_y[b * HH + j] = tanhf(xv[bi] * gm + be);
    }
}

// ======== Kernel 6: reduce fc2 partials + bias -> output x ==================
__global__ __launch_bounds__(256) void finalize_kernel(
    const float* __restrict__ fc2_b, float* __restrict__ out_x)
{
    const int i = blockIdx.x * 256 + threadIdx.x;   // 16384 float4s
    const float4* b4 = (const float4*)fc2_b;
    const float4* p4 = (const float4*)g_fc2_part;
    float4 v = b4[i & (HH / 4 - 1)];
#pragma unroll
    for (int kt = 0; kt < 16; kt++) {
        const float4 p = p4[(size_t)kt * BB * HH / 4 + i];
        v.x += p.x; v.y += p.y; v.z += p.z; v.w += p.w;
    }
    ((float4*)out_x)[i] = v;
}

// ============================ launch ========================================
extern "C" void kernel_launch(void* const* d_in, const int* in_sizes, int n_in,
                              void* d_out, int out_size)
{
    const float* ctx   = (const float*)d_in[0];
    const float* key   = (const float*)d_in[1];
    const float* mask  = (const float*)d_in[2];
    const float* fc1_w = (const float*)d_in[3];
    // d_in[4] = fc1_b (cancels in BatchNorm, unused)
    const float* bn_g  = (const float*)d_in[5];
    const float* bn_b  = (const float*)d_in[6];
    const float* fc2_w = (const float*)d_in[7];
    const float* fc2_b = (const float*)d_in[8];

    float* out_x  = (float*)d_out;              // (B, H)  = 65536 floats
    float* out_At = (float*)d_out + BB * HH;    // (B, S)  = 131072 floats

    attn_pass<<<dim3(SPLITS, BB / WARPS_PER_CTA), 256>>>(ctx, key, mask);
    combine_kernel<<<dim3(BB, 3), 256>>>(out_At);

    // fc1: cat([attn, key]) @ fc1_w.T   (K = 2048, 16 k-splits of 128)
    gemm_splitk<2048, 128, true><<<dim3(16, 16), 256>>>(key, fc1_w);
    bn_tanh_kernel<<<128, 256>>>(bn_g, bn_b);

    // fc2: y @ fc2_w.T                  (K = 1024, 16 k-splits of 64)
    gemm_splitk<1024, 64, false><<<dim3(16, 16), 256>>>(key, fc2_w);
    finalize_kernel<<<64, 256>>>(fc2_b, out_x);
}

// round 16
// speedup vs baseline: 1.0331x; 1.0078x over previous
#include <cuda_runtime.h>
#include <math.h>

#define BB 64
#define SS 2048
#define HH 1024
#define SPLITS 32
#define ROWS_PER_WARP (SS / SPLITS)           // 64
#define WARPS_PER_CTA 8

// ---------------- scratch (no allocations allowed) ----------------
__device__ float g_scores[BB * SS];             // raw attention scores
__device__ float g_pacc[BB * SPLITS * HH];      // partial weighted sums (8 MB)
__device__ float g_pm[BB * SPLITS];             // partial running max
__device__ float g_pl[BB * SPLITS];             // partial exp-sum
__device__ float g_attn[BB * HH];               // combined attention output
__device__ float g_fc1[BB * HH];                // fc1 output (atomic-accumulated)
__device__ float g_y[BB * HH];                  // post-BN-tanh activations

#define FMA2(d, a, b) \
    asm("fma.rn.f32x2 %0, %1, %2, %0;" : "+l"(d) : "l"(a), "l"(b))

// ================= Kernel 1: locality-transposed attention ==================
// grid (SPLITS, BB/8), block 256 = 8 warps. Warp w owns batch b = by*8+w and
// sweeps s in [bx*64, bx*64+64). All 8 warps of a CTA move through the SAME s
// in near-lockstep, so each step the CTA reads rows (s, b0..b0+7): one
// contiguous 32 KB block. ctx streamed with __ldcs (read-once).
// Frozen at R12 form: best of five measured attn variants.
__global__ __launch_bounds__(256) void attn_pass(
    const float* __restrict__ ctx, const float* __restrict__ key,
    const float* __restrict__ mask)
{
    const int w    = threadIdx.x >> 5;
    const int lane = threadIdx.x & 31;
    const int b     = blockIdx.y * WARPS_PER_CTA + w;
    const int split = blockIdx.x;
    const int s0    = split * ROWS_PER_WARP;

    const float4* ctx4 = (const float4*)ctx;
    const float4* key4 = (const float4*)key;

    float4 kk[8];
#pragma unroll
    for (int j = 0; j < 8; j++)
        kk[j] = key4[b * (HH / 4) + j * 32 + lane];

    float4 acc[8];
#pragma unroll
    for (int j = 0; j < 8; j++) acc[j] = make_float4(0.f, 0.f, 0.f, 0.f);
    float m = -1e30f, l = 0.f;

    for (int r = 0; r < ROWS_PER_WARP; r++) {
        const int s = s0 + r;
        const float4* row = ctx4 + (size_t)(s * BB + b) * (HH / 4);
        float4 rv[8];
#pragma unroll
        for (int j = 0; j < 8; j++) rv[j] = __ldcs(&row[j * 32 + lane]);

        float d = 0.f;
#pragma unroll
        for (int j = 0; j < 8; j++)
            d += rv[j].x * kk[j].x + rv[j].y * kk[j].y +
                 rv[j].z * kk[j].z + rv[j].w * kk[j].w;
#pragma unroll
        for (int off = 16; off > 0; off >>= 1)
            d += __shfl_xor_sync(0xffffffffu, d, off);

        d += mask[b * SS + s];
        if (lane == 0) g_scores[b * SS + s] = d;

        if (d > m) {
            const float f = __expf(m - d);
            m = d;
            l *= f;
#pragma unroll
            for (int j = 0; j < 8; j++) {
                acc[j].x *= f; acc[j].y *= f; acc[j].z *= f; acc[j].w *= f;
            }
        }
        const float p = __expf(d - m);
        l += p;
#pragma unroll
        for (int j = 0; j < 8; j++) {
            acc[j].x += p * rv[j].x; acc[j].y += p * rv[j].y;
            acc[j].z += p * rv[j].z; acc[j].w += p * rv[j].w;
        }
    }

    float4* pacc4 = (float4*)g_pacc;
#pragma unroll
    for (int j = 0; j < 8; j++)
        pacc4[(size_t)(b * SPLITS + split) * (HH / 4) + j * 32 + lane] = acc[j];
    if (lane == 0) {
        g_pm[b * SPLITS + split] = m;
        g_pl[b * SPLITS + split] = l;
    }
}

// ====== Kernel 2: combine -> attn | normalize At | init accumulators =======
// grid (B, 4), block 256.
// phase 0/1: attn combine (half of H each, float2). phase 2: At normalize.
// phase 3: init g_fc1 to 0 and out_x to fc2 bias (atomic accumulation targets;
// must re-run every graph replay).
__global__ __launch_bounds__(256) void combine_kernel(
    float* __restrict__ out_At, float* __restrict__ out_x,
    const float* __restrict__ fc2_b)
{
    const int b = blockIdx.x;
    const int tid = threadIdx.x;

    if (blockIdx.y == 3) {
#pragma unroll
        for (int it = 0; it < HH / 256; it++) {
            const int j = it * 256 + tid;
            out_x[b * HH + j] = fc2_b[j];
            g_fc1[b * HH + j] = 0.f;
        }
        return;
    }

    float M = -1e30f;
#pragma unroll
    for (int i = 0; i < SPLITS; i++)
        M = fmaxf(M, g_pm[b * SPLITS + i]);
    float L = 0.f;
#pragma unroll
    for (int i = 0; i < SPLITS; i++)
        L += __expf(g_pm[b * SPLITS + i] - M) * g_pl[b * SPLITS + i];
    const float invL = 1.f / L;

    if (blockIdx.y < 2) {
        const int i2 = blockIdx.y * 256 + tid;     // float2 index, 512 = HH/2
        float2 a = make_float2(0.f, 0.f);
#pragma unroll
        for (int i = 0; i < SPLITS; i++) {
            const float f = __expf(g_pm[b * SPLITS + i] - M);
            const float2 v =
                ((const float2*)g_pacc)[(size_t)(b * SPLITS + i) * (HH / 2) + i2];
            a.x += f * v.x; a.y += f * v.y;
        }
        a.x *= invL; a.y *= invL;
        ((float2*)g_attn)[b * (HH / 2) + i2] = a;
    } else {
        const float4* sc4 = (const float4*)(g_scores + b * SS);
        float4* at4 = (float4*)(out_At + b * SS);
#pragma unroll
        for (int it = 0; it < SS / 4 / 256; it++) {
            const float4 s = sc4[it * 256 + tid];
            at4[it * 256 + tid] = make_float4(
                __expf(s.x - M) * invL, __expf(s.y - M) * invL,
                __expf(s.z - M) * invL, __expf(s.w - M) * invL);
        }
    }
}

// ============ Kernel 3/5: split-K GEMM, atomic-accumulate epilogue ==========
// block 256 (16x16), tile 64b x 64j x KCHUNK. k-major smem, A duplicated so
// both fma.rn.f32x2 operands come pre-packed from shared memory.
// Epilogue: red.global.add.f32 into the 256 KB destination (g_fc1 for fc1,
// bias-initialized out_x for fc2) — no partial buffers, no finalize pass.
template <int K, int KCHUNK, bool CAT>
__global__ __launch_bounds__(256) void gemm_splitk(
    const float* __restrict__ key, const float* __restrict__ W,
    float* __restrict__ dst_ext)
{
    const float* A  = CAT ? g_attn : g_y;
    float* dst      = CAT ? g_fc1 : dst_ext;

    const int tid = threadIdx.x;
    const int j0 = blockIdx.x * 64;
    const int k0 = blockIdx.y * KCHUNK;
    const int tx = tid & 15, ty = tid >> 4;

    __shared__ float As[32][132];   // As[k][2r] = As[k][2r+1] = A[r][k]
    __shared__ float Ws[32][68];    // Ws[k][r]  = W[j0+r][k]

    unsigned long long acc[4][2];
#pragma unroll
    for (int i = 0; i < 4; i++) { acc[i][0] = 0ull; acc[i][1] = 0ull; }

    for (int kk = 0; kk < KCHUNK; kk += 32) {
#pragma unroll
        for (int t = 0; t < 8; t++) {
            const int e = tid + t * 256;
            const int r = e >> 5, c = e & 31;
            const int kg = k0 + kk + c;
            float av;
            if (CAT)
                av = (kg < HH) ? A[r * HH + kg] : key[r * HH + kg - HH];
            else
                av = A[r * K + kg];
            *(float2*)&As[c][2 * r] = make_float2(av, av);
            Ws[c][r] = W[(size_t)(j0 + r) * K + kg];
        }
        __syncthreads();
#pragma unroll
        for (int k = 0; k < 32; k++) {
            const ulonglong2 a01 = *(const ulonglong2*)&As[k][ty * 8];
            const ulonglong2 a23 = *(const ulonglong2*)&As[k][ty * 8 + 4];
            const ulonglong2 wp  = *(const ulonglong2*)&Ws[k][tx * 4];
            FMA2(acc[0][0], a01.x, wp.x); FMA2(acc[0][1], a01.x, wp.y);
            FMA2(acc[1][0], a01.y, wp.x); FMA2(acc[1][1], a01.y, wp.y);
            FMA2(acc[2][0], a23.x, wp.x); FMA2(acc[2][1], a23.x, wp.y);
            FMA2(acc[3][0], a23.y, wp.x); FMA2(acc[3][1], a23.y, wp.y);
        }
        __syncthreads();
    }

#pragma unroll
    for (int bi = 0; bi < 4; bi++) {
        const int b = ty * 4 + bi;
        float* drow = dst + (size_t)b * HH + j0 + tx * 4;
#pragma unroll
        for (int jp = 0; jp < 2; jp++) {
            atomicAdd(drow + jp * 2,
                      __uint_as_float((unsigned)(acc[bi][jp] & 0xffffffffull)));
            atomicAdd(drow + jp * 2 + 1,
                      __uint_as_float((unsigned)(acc[bi][jp] >> 32)));
        }
    }
}

// ======== Kernel 4: BatchNorm(train) + tanh over g_fc1 ====================
// grid 128, block 256: CTA = 8 features x 64 batches, 2 batches/thread-group.
// Input is now the pre-reduced 256 KB g_fc1 (L2-hot) — 2 loads per thread.
// fc1_b is skipped: any per-feature constant cancels exactly in (x - mean).
__global__ __launch_bounds__(256) void bn_tanh_kernel(
    const float* __restrict__ gamma, const float* __restrict__ beta)
{
    __shared__ float rsum[32][9];
    __shared__ float rsq[32][9];

    const int t  = threadIdx.x;
    const int jl = t & 7;
    const int bt = t >> 3;            // 0..31, each covers 2 batches
    const int j  = blockIdx.x * 8 + jl;

    float xv[2];
    float ps = 0.f, pq = 0.f;
#pragma unroll
    for (int bi = 0; bi < 2; bi++) {
        const int b = bt * 2 + bi;
        const float s = g_fc1[b * HH + j];
        xv[bi] = s;
        ps += s;
        pq += s * s;
    }
    rsum[bt][jl] = ps;
    rsq[bt][jl]  = pq;
    __syncthreads();

    float mean = 0.f, msq = 0.f;
#pragma unroll
    for (int g = 0; g < 32; g++) {
        mean += rsum[g][jl];
        msq  += rsq[g][jl];
    }
    mean *= (1.f / BB);
    msq  *= (1.f / BB);
    const float var = msq - mean * mean;
    const float inv = rsqrtf(var + 1e-5f);
    const float gm  = gamma[j] * inv;
    const float be  = beta[j] - mean * gm;

#pragma unroll
    for (int bi = 0; bi < 2; bi++) {
        const int b = bt * 2 + bi;
        g_y[b * HH + j] = tanhf(xv[bi] * gm + be);
    }
}

// ============================ launch ========================================
extern "C" void kernel_launch(void* const* d_in, const int* in_sizes, int n_in,
                              void* d_out, int out_size)
{
    const float* ctx   = (const float*)d_in[0];
    const float* key   = (const float*)d_in[1];
    const float* mask  = (const float*)d_in[2];
    const float* fc1_w = (const float*)d_in[3];
    // d_in[4] = fc1_b (cancels in BatchNorm, unused)
    const float* bn_g  = (const float*)d_in[5];
    const float* bn_b  = (const float*)d_in[6];
    const float* fc2_w = (const float*)d_in[7];
    const float* fc2_b = (const float*)d_in[8];

    float* out_x  = (float*)d_out;              // (B, H)  = 65536 floats
    float* out_At = (float*)d_out + BB * HH;    // (B, S)  = 131072 floats

    attn_pass<<<dim3(SPLITS, BB / WARPS_PER_CTA), 256>>>(ctx, key, mask);
    combine_kernel<<<dim3(BB, 4), 256>>>(out_At, out_x, fc2_b);

    // fc1: cat([attn, key]) @ fc1_w.T   (K = 2048, 16 k-splits of 128)
    gemm_splitk<2048, 128, true><<<dim3(16, 16), 256>>>(key, fc1_w, out_x);
    bn_tanh_kernel<<<128, 256>>>(bn_g, bn_b);

    // fc2: y @ fc2_w.T  (K = 1024, 16 k-splits of 64) -> atomics into out_x
    gemm_splitk<1024, 64, false><<<dim3(16, 16), 256>>>(key, fc2_w, out_x);
}